// round 1
// baseline (speedup 1.0000x reference)
#include <cuda_runtime.h>
#include <math_constants.h>

#define NN 50000
#define EE 500000
#define FF 64
#define HH 4
#define HF 256          // H*F
#define EDIM 64
#define ET (EE + NN)    // 550000 edges incl. self loops

// ---------------- scratch (device globals; no allocation allowed) ----------------
__device__ float  g_xl[NN * HF];        // x @ W_l + b_l
__device__ float  g_xr[NN * HF];        // x @ W_r + b_r
__device__ float  g_lattr[NN * EDIM];   // self-loop edge attr (mean of incoming)
__device__ float  g_cnt[NN];
__device__ float  g_alpha[ET * HH];     // pre-softmax logits, then exp()
__device__ float  g_amax[NN * HH];
__device__ float  g_denom[NN * HH];
__device__ float  g_out[NN * FF];       // head-summed aggregate, then y
__device__ double g_bsum[FF];
__device__ double g_bsq[FF];
__device__ float  g_mean[FF];
__device__ float  g_istd[FF];

// ---------------- helpers ----------------
__device__ __forceinline__ void atomicMaxF(float* addr, float v) {
    if (v >= 0.0f) atomicMax((int*)addr, __float_as_int(v));
    else           atomicMin((unsigned int*)addr, __float_as_uint(v));
}

// ---------------- kernels ----------------
__global__ void k_init() {
    int t = blockIdx.x * blockDim.x + threadIdx.x;
    int stride = gridDim.x * blockDim.x;
    for (int i = t; i < NN * EDIM; i += stride) g_lattr[i] = 0.0f;
    for (int i = t; i < NN; i += stride) g_cnt[i] = 0.0f;
    for (int i = t; i < NN * HH; i += stride) { g_amax[i] = -CUDART_INF_F; g_denom[i] = 0.0f; }
    for (int i = t; i < NN * FF; i += stride) g_out[i] = 0.0f;
    for (int i = t; i < FF; i += stride) { g_bsum[i] = 0.0; g_bsq[i] = 0.0; }
}

// x [N,64] @ W [64,256] + b, for both W_l (threads 0..63) and W_r (threads 64..127).
// 4 rows per block; W read from L1, 4 outputs/thread via float4.
__global__ void k_linear(const float* __restrict__ x,
                         const float* __restrict__ Wl, const float* __restrict__ bl,
                         const float* __restrict__ Wr, const float* __restrict__ br) {
    __shared__ float sx[4 * FF];
    int row0 = blockIdx.x * 4;
    int tx = threadIdx.x;  // 128
    for (int i = tx; i < 4 * FF; i += 128) {
        int r = row0 + (i >> 6);
        sx[i] = (r < NN) ? x[r * FF + (i & 63)] : 0.0f;
    }
    __syncthreads();
    const float* W  = (tx < 64) ? Wl : Wr;
    const float* bv = (tx < 64) ? bl : br;
    float* dst      = (tx < 64) ? g_xl : g_xr;
    int j4 = (tx & 63) * 4;
    float4 bb = *(const float4*)(bv + j4);
    float4 acc0 = bb, acc1 = bb, acc2 = bb, acc3 = bb;
    #pragma unroll
    for (int k = 0; k < FF; k++) {
        float4 w = *(const float4*)(W + k * HF + j4);
        float a0 = sx[0 * FF + k], a1 = sx[1 * FF + k], a2 = sx[2 * FF + k], a3 = sx[3 * FF + k];
        acc0.x += a0 * w.x; acc0.y += a0 * w.y; acc0.z += a0 * w.z; acc0.w += a0 * w.w;
        acc1.x += a1 * w.x; acc1.y += a1 * w.y; acc1.z += a1 * w.z; acc1.w += a1 * w.w;
        acc2.x += a2 * w.x; acc2.y += a2 * w.y; acc2.z += a2 * w.z; acc2.w += a2 * w.w;
        acc3.x += a3 * w.x; acc3.y += a3 * w.y; acc3.z += a3 * w.z; acc3.w += a3 * w.w;
    }
    if (row0 + 0 < NN) *(float4*)(dst + (row0 + 0) * HF + j4) = acc0;
    if (row0 + 1 < NN) *(float4*)(dst + (row0 + 1) * HF + j4) = acc1;
    if (row0 + 2 < NN) *(float4*)(dst + (row0 + 2) * HF + j4) = acc2;
    if (row0 + 3 < NN) *(float4*)(dst + (row0 + 3) * HF + j4) = acc3;
}

// segment-sum edge_attr over dst + count
__global__ void k_loopattr(const int* __restrict__ ei, const float* __restrict__ ea) {
    int t = blockIdx.x * blockDim.x + threadIdx.x;
    if (t >= EE * EDIM) return;
    int e = t >> 6, f = t & 63;
    int dst = ei[EE + e];
    atomicAdd(&g_lattr[dst * EDIM + f], ea[t]);
    if (f == 0) atomicAdd(&g_cnt[dst], 1.0f);
}

__global__ void k_loopdiv() {
    int t = blockIdx.x * blockDim.x + threadIdx.x;
    if (t >= NN * EDIM) return;
    float c = g_cnt[t >> 6];
    g_lattr[t] /= fmaxf(c, 1.0f);
}

// Per-edge: e_emb = ea @ W_e; m = lrelu(xl[src]+xr[dst]+e_emb); alpha[h] = <m_h, att_h>.
// Block = 256 thr (8 warps), 32 edges/block, 4 edges/warp register-tiled.
__global__ void k_alpha(const int* __restrict__ ei, const float* __restrict__ ea,
                        const float* __restrict__ We, const float* __restrict__ att) {
    extern __shared__ float smem[];
    float* sW   = smem;                 // 64*256
    float* sEA  = smem + 16384;         // 32*64
    float* sAtt = smem + 18432;         // 256
    int*   sSrc = (int*)(smem + 18688); // 32
    int*   sDst = (int*)(smem + 18720); // 32

    int tid = threadIdx.x;
    int e0 = blockIdx.x * 32;

    for (int i = tid; i < 4096; i += 256)
        ((float4*)sW)[i] = ((const float4*)We)[i];
    if (tid < 256) sAtt[tid] = att[tid];
    if (tid < 32) {
        int e = e0 + tid;
        int s = 0, d = 0;
        if (e < ET) {
            if (e < EE) { s = ei[e]; d = ei[EE + e]; }
            else        { s = e - EE; d = e - EE; }
        }
        sSrc[tid] = s; sDst[tid] = d;
    }
    for (int idx = tid; idx < 32 * EDIM; idx += 256) {
        int i = idx >> 6, f = idx & 63;
        int e = e0 + i;
        float v = 0.0f;
        if (e < EE) v = ea[e * EDIM + f];
        else if (e < ET) v = g_lattr[(e - EE) * EDIM + f];
        sEA[idx] = v;
    }
    __syncthreads();

    int w = tid >> 5, lane = tid & 31;
    float acc[4][8];
    #pragma unroll
    for (int i = 0; i < 4; i++)
        #pragma unroll
        for (int c = 0; c < 8; c++) acc[i][c] = 0.0f;

    int jA = lane * 4;            // cols jA..jA+3 (heads 0/1)
    int jB = 128 + lane * 4;      // cols jB..jB+3 (heads 2/3)

    #pragma unroll 4
    for (int k = 0; k < 64; k++) {
        float4 wa = *(const float4*)&sW[k * 256 + jA];
        float4 wb = *(const float4*)&sW[k * 256 + jB];
        #pragma unroll
        for (int i = 0; i < 4; i++) {
            float a = sEA[(4 * w + i) * 64 + k];
            acc[i][0] += a * wa.x; acc[i][1] += a * wa.y;
            acc[i][2] += a * wa.z; acc[i][3] += a * wa.w;
            acc[i][4] += a * wb.x; acc[i][5] += a * wb.y;
            acc[i][6] += a * wb.z; acc[i][7] += a * wb.w;
        }
    }

    float attA0 = sAtt[jA], attA1 = sAtt[jA + 1], attA2 = sAtt[jA + 2], attA3 = sAtt[jA + 3];
    float attB0 = sAtt[jB], attB1 = sAtt[jB + 1], attB2 = sAtt[jB + 2], attB3 = sAtt[jB + 3];

    #pragma unroll
    for (int i = 0; i < 4; i++) {
        int e = e0 + 4 * w + i;
        if (e >= ET) break;
        int src = sSrc[4 * w + i], dst = sDst[4 * w + i];
        float4 xla = *(const float4*)&g_xl[src * HF + jA];
        float4 xlb = *(const float4*)&g_xl[src * HF + jB];
        float4 xra = *(const float4*)&g_xr[dst * HF + jA];
        float4 xrb = *(const float4*)&g_xr[dst * HF + jB];
        float m, pA = 0.0f, pB = 0.0f;
        m = acc[i][0] + xla.x + xra.x; m = (m > 0.f) ? m : 0.2f * m; pA += m * attA0;
        m = acc[i][1] + xla.y + xra.y; m = (m > 0.f) ? m : 0.2f * m; pA += m * attA1;
        m = acc[i][2] + xla.z + xra.z; m = (m > 0.f) ? m : 0.2f * m; pA += m * attA2;
        m = acc[i][3] + xla.w + xra.w; m = (m > 0.f) ? m : 0.2f * m; pA += m * attA3;
        m = acc[i][4] + xlb.x + xrb.x; m = (m > 0.f) ? m : 0.2f * m; pB += m * attB0;
        m = acc[i][5] + xlb.y + xrb.y; m = (m > 0.f) ? m : 0.2f * m; pB += m * attB1;
        m = acc[i][6] + xlb.z + xrb.z; m = (m > 0.f) ? m : 0.2f * m; pB += m * attB2;
        m = acc[i][7] + xlb.w + xrb.w; m = (m > 0.f) ? m : 0.2f * m; pB += m * attB3;
        #pragma unroll
        for (int d = 1; d < 16; d <<= 1) {
            pA += __shfl_xor_sync(0xffffffffu, pA, d);
            pB += __shfl_xor_sync(0xffffffffu, pB, d);
        }
        if (lane == 0 || lane == 16) {
            int hA = lane >> 4;      // 0 or 1
            int hB = hA + 2;         // 2 or 3
            g_alpha[e * HH + hA] = pA;
            g_alpha[e * HH + hB] = pB;
            atomicMaxF(&g_amax[dst * HH + hA], pA);
            atomicMaxF(&g_amax[dst * HH + hB], pB);
        }
    }
}

__global__ void k_denom(const int* __restrict__ ei) {
    int t = blockIdx.x * blockDim.x + threadIdx.x;
    if (t >= ET * HH) return;
    int e = t >> 2, h = t & 3;
    int dst = (e < EE) ? ei[EE + e] : (e - EE);
    float ex = expf(g_alpha[t] - g_amax[dst * HH + h]);
    g_alpha[t] = ex;
    atomicAdd(&g_denom[dst * HH + h], ex);
}

// One warp per edge; head-mean folded: out[dst,f] += sum_h w_h * xl[src, h*64+f]
__global__ void k_aggr(const int* __restrict__ ei) {
    int gw = (blockIdx.x * blockDim.x + threadIdx.x) >> 5;
    int lane = threadIdx.x & 31;
    if (gw >= ET) return;
    int e = gw;
    int src = (e < EE) ? ei[e] : (e - EE);
    int dst = (e < EE) ? ei[EE + e] : (e - EE);
    float w0 = g_alpha[e * HH + 0] / (g_denom[dst * HH + 0] + 1e-16f);
    float w1 = g_alpha[e * HH + 1] / (g_denom[dst * HH + 1] + 1e-16f);
    float w2 = g_alpha[e * HH + 2] / (g_denom[dst * HH + 2] + 1e-16f);
    float w3 = g_alpha[e * HH + 3] / (g_denom[dst * HH + 3] + 1e-16f);
    int f = lane * 2;
    const float* xb = g_xl + src * HF;
    float2 a0 = *(const float2*)(xb + 0 * 64 + f);
    float2 a1 = *(const float2*)(xb + 1 * 64 + f);
    float2 a2 = *(const float2*)(xb + 2 * 64 + f);
    float2 a3 = *(const float2*)(xb + 3 * 64 + f);
    float vx = w0 * a0.x + w1 * a1.x + w2 * a2.x + w3 * a3.x;
    float vy = w0 * a0.y + w1 * a1.y + w2 * a2.y + w3 * a3.y;
    atomicAdd(&g_out[dst * FF + f],     vx);
    atomicAdd(&g_out[dst * FF + f + 1], vy);
}

// y = out/H + bias; accumulate BN sum/sumsq (double atomics, per-block reduced)
__global__ void k_bnstat(const float* __restrict__ bias) {
    __shared__ float ss[4][64], sq[4][64];
    int f = threadIdx.x;      // 64
    int ty = threadIdx.y;     // 4
    float b = bias[f];
    float s = 0.0f, q = 0.0f;
    for (int r = blockIdx.x * 4 + ty; r < NN; r += gridDim.x * 4) {
        float y = g_out[r * FF + f] * 0.25f + b;
        g_out[r * FF + f] = y;
        s += y; q += y * y;
    }
    ss[ty][f] = s; sq[ty][f] = q;
    __syncthreads();
    if (ty == 0) {
        float S = ss[0][f] + ss[1][f] + ss[2][f] + ss[3][f];
        float Q = sq[0][f] + sq[1][f] + sq[2][f] + sq[3][f];
        atomicAdd(&g_bsum[f], (double)S);
        atomicAdd(&g_bsq[f], (double)Q);
    }
}

__global__ void k_bnfin() {
    int f = threadIdx.x;
    double m = g_bsum[f] / (double)NN;
    double v = g_bsq[f] / (double)NN - m * m;
    g_mean[f] = (float)m;
    g_istd[f] = rsqrtf((float)v + 1e-5f);
}

__global__ void k_norm(const float* __restrict__ gamma, const float* __restrict__ beta,
                       float* __restrict__ out) {
    int t = blockIdx.x * blockDim.x + threadIdx.x;
    if (t >= NN * FF) return;
    int f = t & 63;
    float y = (g_out[t] - g_mean[f]) * g_istd[f] * gamma[f] + beta[f];
    out[t] = fmaxf(y, 0.0f);
}

// ---------------- launch ----------------
extern "C" void kernel_launch(void* const* d_in, const int* in_sizes, int n_in,
                              void* d_out, int out_size) {
    const float* x     = (const float*)d_in[0];
    const int*   ei    = (const int*)d_in[1];
    const float* ea    = (const float*)d_in[2];
    const float* Wl    = (const float*)d_in[3];
    const float* bl    = (const float*)d_in[4];
    const float* Wr    = (const float*)d_in[5];
    const float* br    = (const float*)d_in[6];
    const float* We    = (const float*)d_in[7];
    const float* att   = (const float*)d_in[8];
    const float* bias  = (const float*)d_in[9];
    const float* gamma = (const float*)d_in[10];
    const float* beta  = (const float*)d_in[11];
    float* out = (float*)d_out;

    static const int ALPHA_SMEM = 75008;
    cudaFuncSetAttribute(k_alpha, cudaFuncAttributeMaxDynamicSharedMemorySize, ALPHA_SMEM);

    k_init<<<4096, 256>>>();
    k_linear<<<(NN + 3) / 4, 128>>>(x, Wl, bl, Wr, br);
    k_loopattr<<<(EE * EDIM) / 256, 256>>>(ei, ea);
    k_loopdiv<<<(NN * EDIM + 255) / 256, 256>>>();
    k_alpha<<<(ET + 31) / 32, 256, ALPHA_SMEM>>>(ei, ea, We, att);
    k_denom<<<(ET * HH + 255) / 256, 256>>>(ei);
    k_aggr<<<(ET * 32 + 255) / 256, 256>>>(ei);
    k_bnstat<<<256, dim3(64, 4)>>>(bias);
    k_bnfin<<<1, 64>>>();
    k_norm<<<(NN * FF + 255) / 256, 256>>>(gamma, beta, out);
}

// round 4
// speedup vs baseline: 1.2028x; 1.2028x over previous
#include <cuda_runtime.h>
#include <math_constants.h>

#define NN 50000
#define EE 500000
#define FF 64
#define HH 4
#define HF 256          // H*F
#define EDIM 64
#define ET (EE + NN)    // 550000 edges incl. self loops

typedef unsigned long long u64;

// ---------------- scratch (device globals; no allocation allowed) ----------------
__device__ float  g_xl[NN * HF];        // x @ W_l + b_l
__device__ float  g_xr[NN * HF];        // x @ W_r + b_r
__device__ float  g_lattr[NN * EDIM];   // self-loop edge attr sums (divided in k_alpha staging)
__device__ float  g_cnt[NN];
__device__ float  g_alpha[ET * HH];     // pre-softmax logits, then exp()
__device__ float  g_amax[NN * HH];
__device__ float  g_denom[NN * HH];
__device__ float  g_out[NN * FF];       // head-summed aggregate, then y
__device__ double g_bsum[FF];
__device__ double g_bsq[FF];
__device__ float  g_mean[FF];
__device__ float  g_istd[FF];

// ---------------- helpers ----------------
__device__ __forceinline__ void atomicMaxF(float* addr, float v) {
    if (v >= 0.0f) atomicMax((int*)addr, __float_as_int(v));
    else           atomicMin((unsigned int*)addr, __float_as_uint(v));
}
__device__ __forceinline__ u64 pack2(float lo, float hi) {
    u64 r; asm("mov.b64 %0, {%1, %2};" : "=l"(r) : "f"(lo), "f"(hi)); return r;
}
__device__ __forceinline__ float2 unpack2(u64 v) {
    float2 r; asm("mov.b64 {%0, %1}, %2;" : "=f"(r.x), "=f"(r.y) : "l"(v)); return r;
}
__device__ __forceinline__ u64 ffma2(u64 a, u64 b, u64 c) {
    u64 d; asm("fma.rn.f32x2 %0, %1, %2, %3;" : "=l"(d) : "l"(a), "l"(b), "l"(c)); return d;
}
// vector atomic add via the official intrinsic (CUDA 12.8+, sm_90+)
__device__ __forceinline__ void red4(float* addr, float4 v) {
    atomicAdd((float4*)addr, v);
}

// ---------------- kernels ----------------
__global__ void k_init() {
    int t = blockIdx.x * blockDim.x + threadIdx.x;
    int stride = gridDim.x * blockDim.x;
    for (int i = t; i < NN * EDIM; i += stride) g_lattr[i] = 0.0f;
    for (int i = t; i < NN; i += stride) g_cnt[i] = 0.0f;
    for (int i = t; i < NN * HH; i += stride) { g_amax[i] = -CUDART_INF_F; g_denom[i] = 0.0f; }
    for (int i = t; i < NN * FF; i += stride) g_out[i] = 0.0f;
    for (int i = t; i < FF; i += stride) { g_bsum[i] = 0.0; g_bsq[i] = 0.0; }
}

// x [N,64] @ W [64,256] + b, for both W_l (threads 0..63) and W_r (threads 64..127).
// 4 rows per block; f32x2 packed FMA.
__global__ void k_linear(const float* __restrict__ x,
                         const float* __restrict__ Wl, const float* __restrict__ bl,
                         const float* __restrict__ Wr, const float* __restrict__ br) {
    __shared__ float sx[4 * FF];
    int row0 = blockIdx.x * 4;
    int tx = threadIdx.x;  // 128
    for (int i = tx; i < 4 * FF; i += 128) {
        int r = row0 + (i >> 6);
        sx[i] = (r < NN) ? x[r * FF + (i & 63)] : 0.0f;
    }
    __syncthreads();
    const float* W  = (tx < 64) ? Wl : Wr;
    const float* bv = (tx < 64) ? bl : br;
    float* dst      = (tx < 64) ? g_xl : g_xr;
    int j4 = (tx & 63) * 4;
    float4 bb = *(const float4*)(bv + j4);
    u64 acc[4][2];
    #pragma unroll
    for (int r = 0; r < 4; r++) { acc[r][0] = pack2(bb.x, bb.y); acc[r][1] = pack2(bb.z, bb.w); }
    #pragma unroll 4
    for (int k = 0; k < FF; k++) {
        float4 w = *(const float4*)(W + k * HF + j4);
        u64 w0 = pack2(w.x, w.y), w1 = pack2(w.z, w.w);
        #pragma unroll
        for (int r = 0; r < 4; r++) {
            u64 aa = pack2(sx[r * FF + k], sx[r * FF + k]);
            acc[r][0] = ffma2(w0, aa, acc[r][0]);
            acc[r][1] = ffma2(w1, aa, acc[r][1]);
        }
    }
    #pragma unroll
    for (int r = 0; r < 4; r++) {
        if (row0 + r < NN) {
            float2 lo = unpack2(acc[r][0]), hi = unpack2(acc[r][1]);
            *(float4*)(dst + (row0 + r) * HF + j4) = make_float4(lo.x, lo.y, hi.x, hi.y);
        }
    }
}

// segment-sum edge_attr over dst + count, vector atomics (16 threads/edge, 4 floats each)
__global__ void k_loopattr(const int* __restrict__ ei, const float* __restrict__ ea) {
    int t = blockIdx.x * blockDim.x + threadIdx.x;   // EE*16 threads
    int e = t >> 4, q = t & 15;
    int dst = ei[EE + e];
    float4 v = ((const float4*)ea)[e * 16 + q];
    red4(&g_lattr[dst * EDIM + q * 4], v);
    if (q == 0) atomicAdd(&g_cnt[dst], 1.0f);
}

// Per-edge: e_emb = ea @ W_e; m = lrelu(xl[src]+xr[dst]+e_emb); alpha[h] = <m_h, att_h>.
// Block = 256 thr (8 warps), 64 edges/block, 8 edges/warp, f32x2 packed FMA.
// Self-loop attr divide (mean) folded into staging.
__global__ void __launch_bounds__(256, 2)
k_alpha(const int* __restrict__ ei, const float* __restrict__ ea,
        const float* __restrict__ We, const float* __restrict__ att) {
    extern __shared__ float smem[];
    float* sW   = smem;                         // 16384 f = 65536 B
    u64*   sEA2 = (u64*)(smem + 16384);         // 64*64 u64 = 32768 B
    float* sAtt = smem + 16384 + 8192;          // 256 f
    int*   sSrc = (int*)(sAtt + 256);           // 64
    int*   sDst = (int*)(sAtt + 320);           // 64

    int tid = threadIdx.x;
    int e0 = blockIdx.x * 64;

    for (int i = tid; i < 4096; i += 256)
        ((float4*)sW)[i] = ((const float4*)We)[i];
    if (tid < 256) sAtt[tid] = att[tid];
    if (tid < 64) {
        int e = e0 + tid;
        int s = 0, d = 0;
        if (e < ET) {
            if (e < EE) { s = ei[e]; d = ei[EE + e]; }
            else        { s = e - EE; d = e - EE; }
        }
        sSrc[tid] = s; sDst[tid] = d;
    }
    for (int idx = tid; idx < 64 * 16; idx += 256) {   // 64 edges x 16 float4 groups
        int i = idx >> 4, g = idx & 15;
        int e = e0 + i;
        float4 v = make_float4(0.f, 0.f, 0.f, 0.f);
        if (e < EE) {
            v = ((const float4*)ea)[e * 16 + g];
        } else if (e < ET) {
            int n = e - EE;
            v = ((const float4*)g_lattr)[n * 16 + g];
            float inv = 1.0f / fmaxf(g_cnt[n], 1.0f);
            v.x *= inv; v.y *= inv; v.z *= inv; v.w *= inv;
        }
        int f = g * 4;
        sEA2[i * 64 + f + 0] = pack2(v.x, v.x);
        sEA2[i * 64 + f + 1] = pack2(v.y, v.y);
        sEA2[i * 64 + f + 2] = pack2(v.z, v.z);
        sEA2[i * 64 + f + 3] = pack2(v.w, v.w);
    }
    __syncthreads();

    int w = tid >> 5, lane = tid & 31;
    int be = 8 * w;                 // first edge of this warp within block
    int jA = lane * 4;              // cols jA..jA+3 (heads 0/1 region)
    int jB = 128 + lane * 4;        // cols jB..jB+3 (heads 2/3 region)

    u64 acc[8][4];
    #pragma unroll
    for (int i = 0; i < 8; i++)
        #pragma unroll
        for (int c = 0; c < 4; c++) acc[i][c] = 0ULL;

    #pragma unroll 2
    for (int k = 0; k < 64; k++) {
        float4 wa = *(const float4*)&sW[k * 256 + jA];
        float4 wb = *(const float4*)&sW[k * 256 + jB];
        u64 w0 = pack2(wa.x, wa.y), w1 = pack2(wa.z, wa.w);
        u64 w2 = pack2(wb.x, wb.y), w3 = pack2(wb.z, wb.w);
        const u64* ek = sEA2 + be * 64 + k;
        #pragma unroll
        for (int i = 0; i < 8; i++) {
            u64 aa = ek[i * 64];
            acc[i][0] = ffma2(w0, aa, acc[i][0]);
            acc[i][1] = ffma2(w1, aa, acc[i][1]);
            acc[i][2] = ffma2(w2, aa, acc[i][2]);
            acc[i][3] = ffma2(w3, aa, acc[i][3]);
        }
    }

    float attA0 = sAtt[jA], attA1 = sAtt[jA + 1], attA2 = sAtt[jA + 2], attA3 = sAtt[jA + 3];
    float attB0 = sAtt[jB], attB1 = sAtt[jB + 1], attB2 = sAtt[jB + 2], attB3 = sAtt[jB + 3];

    #pragma unroll
    for (int i = 0; i < 8; i++) {
        int e = e0 + be + i;
        if (e >= ET) break;
        int src = sSrc[be + i], dst = sDst[be + i];
        float4 xla = *(const float4*)&g_xl[src * HF + jA];
        float4 xlb = *(const float4*)&g_xl[src * HF + jB];
        float4 xra = *(const float4*)&g_xr[dst * HF + jA];
        float4 xrb = *(const float4*)&g_xr[dst * HF + jB];
        float2 c0 = unpack2(acc[i][0]), c1 = unpack2(acc[i][1]);
        float2 c2 = unpack2(acc[i][2]), c3 = unpack2(acc[i][3]);
        float m, pA = 0.0f, pB = 0.0f;
        m = c0.x + xla.x + xra.x; m = (m > 0.f) ? m : 0.2f * m; pA += m * attA0;
        m = c0.y + xla.y + xra.y; m = (m > 0.f) ? m : 0.2f * m; pA += m * attA1;
        m = c1.x + xla.z + xra.z; m = (m > 0.f) ? m : 0.2f * m; pA += m * attA2;
        m = c1.y + xla.w + xra.w; m = (m > 0.f) ? m : 0.2f * m; pA += m * attA3;
        m = c2.x + xlb.x + xrb.x; m = (m > 0.f) ? m : 0.2f * m; pB += m * attB0;
        m = c2.y + xlb.y + xrb.y; m = (m > 0.f) ? m : 0.2f * m; pB += m * attB1;
        m = c3.x + xlb.z + xrb.z; m = (m > 0.f) ? m : 0.2f * m; pB += m * attB2;
        m = c3.y + xlb.w + xrb.w; m = (m > 0.f) ? m : 0.2f * m; pB += m * attB3;
        #pragma unroll
        for (int d = 1; d < 16; d <<= 1) {
            pA += __shfl_xor_sync(0xffffffffu, pA, d);
            pB += __shfl_xor_sync(0xffffffffu, pB, d);
        }
        if (lane == 0 || lane == 16) {
            int hA = lane >> 4;      // 0 or 1
            int hB = hA + 2;         // 2 or 3
            g_alpha[e * HH + hA] = pA;
            g_alpha[e * HH + hB] = pB;
            atomicMaxF(&g_amax[dst * HH + hA], pA);
            atomicMaxF(&g_amax[dst * HH + hB], pB);
        }
    }
}

// exp + denominator accumulation, one thread per edge (4 heads vectorized)
__global__ void k_denom(const int* __restrict__ ei) {
    int e = blockIdx.x * blockDim.x + threadIdx.x;
    if (e >= ET) return;
    int dst = (e < EE) ? ei[EE + e] : (e - EE);
    float4 a = ((const float4*)g_alpha)[e];
    float4 mx = ((const float4*)g_amax)[dst];
    float4 ex;
    ex.x = __expf(a.x - mx.x);
    ex.y = __expf(a.y - mx.y);
    ex.z = __expf(a.z - mx.z);
    ex.w = __expf(a.w - mx.w);
    ((float4*)g_alpha)[e] = ex;
    red4(&g_denom[dst * HH], ex);
}

// 2 edges per warp (16 lanes/edge, 4 floats/lane); head-mean folded into weights.
__global__ void k_aggr(const int* __restrict__ ei) {
    int gw = (blockIdx.x * blockDim.x + threadIdx.x) >> 5;
    int lane = threadIdx.x & 31;
    int sub = lane >> 4;            // 0 or 1
    int l16 = lane & 15;
    int e = gw * 2 + sub;           // ET even -> exact coverage
    int src = (e < EE) ? ei[e] : (e - EE);
    int dst = (e < EE) ? ei[EE + e] : (e - EE);
    float wj = 0.0f;
    if (l16 < 4)
        wj = g_alpha[e * HH + l16] / (g_denom[dst * HH + l16] + 1e-16f);
    int base = sub << 4;
    float w0 = __shfl_sync(0xffffffffu, wj, base + 0);
    float w1 = __shfl_sync(0xffffffffu, wj, base + 1);
    float w2 = __shfl_sync(0xffffffffu, wj, base + 2);
    float w3 = __shfl_sync(0xffffffffu, wj, base + 3);
    int f = l16 * 4;
    const float* xb = g_xl + src * HF;
    float4 a0 = *(const float4*)(xb + 0 * 64 + f);
    float4 a1 = *(const float4*)(xb + 1 * 64 + f);
    float4 a2 = *(const float4*)(xb + 2 * 64 + f);
    float4 a3 = *(const float4*)(xb + 3 * 64 + f);
    float4 v;
    v.x = w0 * a0.x + w1 * a1.x + w2 * a2.x + w3 * a3.x;
    v.y = w0 * a0.y + w1 * a1.y + w2 * a2.y + w3 * a3.y;
    v.z = w0 * a0.z + w1 * a1.z + w2 * a2.z + w3 * a3.z;
    v.w = w0 * a0.w + w1 * a1.w + w2 * a2.w + w3 * a3.w;
    red4(&g_out[dst * FF + f], v);
}

// y = out/H + bias; accumulate BN sum/sumsq
__global__ void k_bnstat(const float* __restrict__ bias) {
    __shared__ float ss[4][64], sq[4][64];
    int f = threadIdx.x;      // 64
    int ty = threadIdx.y;     // 4
    float b = bias[f];
    float s = 0.0f, q = 0.0f;
    for (int r = blockIdx.x * 4 + ty; r < NN; r += gridDim.x * 4) {
        float y = g_out[r * FF + f] * 0.25f + b;
        g_out[r * FF + f] = y;
        s += y; q += y * y;
    }
    ss[ty][f] = s; sq[ty][f] = q;
    __syncthreads();
    if (ty == 0) {
        float S = ss[0][f] + ss[1][f] + ss[2][f] + ss[3][f];
        float Q = sq[0][f] + sq[1][f] + sq[2][f] + sq[3][f];
        atomicAdd(&g_bsum[f], (double)S);
        atomicAdd(&g_bsq[f], (double)Q);
    }
}

__global__ void k_bnfin() {
    int f = threadIdx.x;
    double m = g_bsum[f] / (double)NN;
    double v = g_bsq[f] / (double)NN - m * m;
    g_mean[f] = (float)m;
    g_istd[f] = rsqrtf((float)v + 1e-5f);
}

__global__ void k_norm(const float* __restrict__ gamma, const float* __restrict__ beta,
                       float* __restrict__ out) {
    int t = blockIdx.x * blockDim.x + threadIdx.x;
    if (t >= NN * FF) return;
    int f = t & 63;
    float y = (g_out[t] - g_mean[f]) * g_istd[f] * gamma[f] + beta[f];
    out[t] = fmaxf(y, 0.0f);
}

// ---------------- launch ----------------
extern "C" void kernel_launch(void* const* d_in, const int* in_sizes, int n_in,
                              void* d_out, int out_size) {
    const float* x     = (const float*)d_in[0];
    const int*   ei    = (const int*)d_in[1];
    const float* ea    = (const float*)d_in[2];
    const float* Wl    = (const float*)d_in[3];
    const float* bl    = (const float*)d_in[4];
    const float* Wr    = (const float*)d_in[5];
    const float* br    = (const float*)d_in[6];
    const float* We    = (const float*)d_in[7];
    const float* att   = (const float*)d_in[8];
    const float* bias  = (const float*)d_in[9];
    const float* gamma = (const float*)d_in[10];
    const float* beta  = (const float*)d_in[11];
    float* out = (float*)d_out;

    static const int ALPHA_SMEM = 65536 + 32768 + 1024 + 256 + 256;  // 99840
    cudaFuncSetAttribute(k_alpha, cudaFuncAttributeMaxDynamicSharedMemorySize, ALPHA_SMEM);

    k_init<<<4096, 256>>>();
    k_linear<<<(NN + 3) / 4, 128>>>(x, Wl, bl, Wr, br);
    k_loopattr<<<(EE * 16) / 256, 256>>>(ei, ea);
    k_alpha<<<(ET + 63) / 64, 256, ALPHA_SMEM>>>(ei, ea, We, att);
    k_denom<<<(ET + 255) / 256, 256>>>(ei);
    k_aggr<<<(ET / 2 * 32) / 256, 256>>>(ei);
    k_bnstat<<<256, dim3(64, 4)>>>(bias);
    k_bnfin<<<1, 64>>>();
    k_norm<<<(NN * FF + 255) / 256, 256>>>(gamma, beta, out);
}